// round 7
// baseline (speedup 1.0000x reference)
#include <cuda_runtime.h>
#include <cuda_fp16.h>
#include <cstdint>

#define NMAX 50000
#define EMAX 800000
#define NNZMAX (EMAX + NMAX)
#define D 128
#define APITCH 136   // padded row pitch in halves (272B): conflict-free ldmatrix
#define NB 148       // persistent-kernel blocks (1 per SM, guaranteed co-resident)
#define NT 512

// ---------------- scratch (device globals: allocation-free) ----------------
__device__ __half g_x16[NMAX * D];
__device__ __half g_h16[NMAX * D];
__device__ __half g_a16[NMAX * D];
__device__ int    g_cnt[NMAX];
__device__ float  g_dis[NMAX];
__device__ int    g_rowptr[NMAX + 1];
__device__ int    g_cursor[NMAX];
__device__ int    g_col[NNZMAX];
__device__ float  g_val[NNZMAX];
__device__ int    g_bsum[NB];
__device__ int    g_boff[NB];
__device__ int    g_bar_count;
__device__ volatile int g_bar_gen;

// ---------------- grid barrier (co-resident grid, deterministic) -----------
__device__ __forceinline__ void grid_barrier() {
    __syncthreads();
    if (threadIdx.x == 0) {
        __threadfence();
        int gen = g_bar_gen;
        if (atomicAdd(&g_bar_count, 1) == NB - 1) {
            g_bar_count = 0;
            __threadfence();
            g_bar_gen = gen + 1;
        } else {
            while (g_bar_gen == gen) __nanosleep(64);
        }
        __threadfence();
    }
    __syncthreads();
}

// ---------------- mma helpers ----------------
__device__ __forceinline__ uint32_t smem_u32(const void* p) {
    return (uint32_t)__cvta_generic_to_shared(p);
}
__device__ __forceinline__ void ldmA(uint32_t* r, uint32_t addr) {
    asm volatile("ldmatrix.sync.aligned.m8n8.x4.shared.b16 {%0,%1,%2,%3}, [%4];"
        : "=r"(r[0]), "=r"(r[1]), "=r"(r[2]), "=r"(r[3]) : "r"(addr));
}
__device__ __forceinline__ void ldmB(uint32_t* r, uint32_t addr) {
    asm volatile("ldmatrix.sync.aligned.m8n8.x2.trans.shared.b16 {%0,%1}, [%2];"
        : "=r"(r[0]), "=r"(r[1]) : "r"(addr));
}
__device__ __forceinline__ void mma16816(float* c, const uint32_t* a, const uint32_t* b) {
    asm volatile("mma.sync.aligned.m16n8k16.row.col.f32.f16.f16.f32 "
        "{%0,%1,%2,%3}, {%4,%5,%6,%7}, {%8,%9}, {%0,%1,%2,%3};"
        : "+f"(c[0]), "+f"(c[1]), "+f"(c[2]), "+f"(c[3])
        : "r"(a[0]), "r"(a[1]), "r"(a[2]), "r"(a[3]), "r"(b[0]), "r"(b[1]));
}

// ---------------- fused CSR build + x->fp16 convert (one launch) -----------
__global__ void __launch_bounds__(NT, 1) k_build(const float* __restrict__ x,
                                                 const int* __restrict__ ei,
                                                 int n, int e) {
    const int t = threadIdx.x;
    const int b = blockIdx.x;
    const int tid = b * NT + t;
    const int T = NB * NT;
    const int* src = ei;
    const int* dst = ei + e;

    // phase 0: zero counts + convert x to fp16
    for (int i = tid; i < n; i += T) g_cnt[i] = 0;
    {
        int n4 = n * (D / 4);
        const float4* x4 = (const float4*)x;
        uint2* o2 = (uint2*)g_x16;
        for (int i = tid; i < n4; i += T) {
            float4 v = x4[i];
            __half2 h0 = __floats2half2_rn(v.x, v.y);
            __half2 h1 = __floats2half2_rn(v.z, v.w);
            uint2 r;
            r.x = *reinterpret_cast<uint32_t*>(&h0);
            r.y = *reinterpret_cast<uint32_t*>(&h1);
            o2[i] = r;
        }
    }
    grid_barrier();

    // phase 1: in-degree count (edges only)
    for (int i = tid; i < e; i += T) atomicAdd(&g_cnt[dst[i]], 1);
    grid_barrier();

    // phase 2: per-block contiguous chunk: v = cnt+1, dis = rsqrt(v), block sum
    const int chunk = (n + NB - 1) / NB;   // <= NT for n <= 50000
    const int i0 = b * chunk;
    const int i1 = min(i0 + chunk, n);
    const int idx = i0 + t;
    int v = 0;
    float my_dis = 0.f;
    if (idx < i1) {
        v = __ldcg(&g_cnt[idx]) + 1;
        my_dis = rsqrtf((float)v);
        g_dis[idx] = my_dis;
    }
    {
        int s = v;
        #pragma unroll
        for (int o = 16; o; o >>= 1) s += __shfl_down_sync(0xffffffffu, s, o);
        __shared__ int ws[NT / 32];
        if ((t & 31) == 0) ws[t >> 5] = s;
        __syncthreads();
        if (t < NT / 32) {
            int xx = ws[t];
            #pragma unroll
            for (int o = NT / 64; o; o >>= 1) xx += __shfl_down_sync(0xffffu, xx, o);
            if (t == 0) g_bsum[b] = xx;
        }
    }
    grid_barrier();

    // phase 3: block 0 scans NB block sums
    if (b == 0) {
        __shared__ int sc[256];
        int vv = (t < NB) ? __ldcg(&g_bsum[t]) : 0;
        if (t < 256) sc[t] = vv;
        __syncthreads();
        #pragma unroll
        for (int o = 1; o < 256; o <<= 1) {
            int xx = (t >= o && t < 256) ? sc[t - o] : 0;
            __syncthreads();
            if (t < 256) sc[t] += xx;
            __syncthreads();
        }
        if (t < NB) g_boff[t] = sc[t] - vv;
        if (t == NB - 1) g_rowptr[n] = sc[t];
    }
    grid_barrier();

    // phase 4: block-local exclusive scan -> rowptr; self-loop entry + cursor
    {
        int lane = t & 31, w = t >> 5;
        int xinc = v;
        #pragma unroll
        for (int o = 1; o < 32; o <<= 1) {
            int y = __shfl_up_sync(0xffffffffu, xinc, o);
            if (lane >= o) xinc += y;
        }
        __shared__ int wsum[NT / 32];
        if (lane == 31) wsum[w] = xinc;
        __syncthreads();
        if (t < NT / 32) {
            int y = wsum[t], z = y;
            #pragma unroll
            for (int o = 1; o < NT / 32; o <<= 1) {
                int q = __shfl_up_sync(0xffffu, z, o);
                if (t >= o) z += q;
            }
            wsum[t] = z - y;
        }
        __syncthreads();
        int excl = __ldcg(&g_boff[b]) + wsum[w] + xinc - v;
        if (idx < i1) {
            g_rowptr[idx] = excl;
            g_col[excl] = idx;
            g_val[excl] = my_dis * my_dis;
            g_cursor[idx] = excl + 1;
        }
    }
    grid_barrier();

    // phase 5: fill edge entries
    for (int i = tid; i < e; i += T) {
        int sI = src[i], dI = dst[i];
        int p = atomicAdd(&g_cursor[dI], 1);
        g_col[p] = sI;
        g_val[p] = __ldcg(&g_dis[sI]) * __ldcg(&g_dis[dI]);
    }
}

// ---------------- GEMM via HMMA: out16 = in16 @ W (W fp32 in gmem) ----------
__global__ void k_gemm_mma(const __half* __restrict__ in, const float* __restrict__ Wf,
                           __half* __restrict__ out, int nrows) {
    extern __shared__ __half sm16[];
    __half* As = sm16;                  // 128 x APITCH
    __half* Ws = sm16 + 128 * APITCH;   // 128 x APITCH
    int t = threadIdx.x;
    int row0 = blockIdx.x * 128;

    #pragma unroll
    for (int i = t; i < 128 * 32; i += 256) {
        int r = i >> 5, c4 = i & 31;
        float4 v = ((const float4*)Wf)[r * 32 + c4];
        __half2 h0 = __floats2half2_rn(v.x, v.y);
        __half2 h1 = __floats2half2_rn(v.z, v.w);
        *(__half2*)(Ws + r * APITCH + c4 * 4)     = h0;
        *(__half2*)(Ws + r * APITCH + c4 * 4 + 2) = h1;
    }
    #pragma unroll
    for (int i = t; i < 128 * 16; i += 256) {
        int r = i >> 4, c8 = i & 15;
        int gr = row0 + r;
        uint4 v = make_uint4(0u, 0u, 0u, 0u);
        if (gr < nrows) v = ((const uint4*)(in + gr * D))[c8];
        *(uint4*)(As + r * APITCH + c8 * 8) = v;
    }
    __syncthreads();

    int wid = t >> 5, lane = t & 31;
    int wm = wid & 3;
    int wn = wid >> 2;

    float c[2][8][4];
    #pragma unroll
    for (int mi = 0; mi < 2; ++mi)
        #pragma unroll
        for (int ni = 0; ni < 8; ++ni)
            #pragma unroll
            for (int j = 0; j < 4; ++j) c[mi][ni][j] = 0.f;

    int arow = wm * 32 + (lane & 15);
    int acol_sel = (lane >> 4) * 8;
    int brow = lane & 15;
    int bcol0 = wn * 64;

    #pragma unroll
    for (int k0 = 0; k0 < 128; k0 += 16) {
        uint32_t a[2][4];
        #pragma unroll
        for (int mi = 0; mi < 2; ++mi) {
            uint32_t addr = smem_u32(As + (arow + mi * 16) * APITCH + k0 + acol_sel);
            ldmA(a[mi], addr);
        }
        uint32_t bfrag[8][2];
        #pragma unroll
        for (int ni = 0; ni < 8; ++ni) {
            uint32_t addr = smem_u32(Ws + (k0 + brow) * APITCH + bcol0 + ni * 8);
            ldmB(bfrag[ni], addr);
        }
        #pragma unroll
        for (int mi = 0; mi < 2; ++mi)
            #pragma unroll
            for (int ni = 0; ni < 8; ++ni)
                mma16816(c[mi][ni], a[mi], bfrag[ni]);
    }

    int r = lane >> 2, cc = (lane & 3) * 2;
    #pragma unroll
    for (int mi = 0; mi < 2; ++mi) {
        int gr0 = row0 + wm * 32 + mi * 16 + r;
        #pragma unroll
        for (int ni = 0; ni < 8; ++ni) {
            int col = wn * 64 + ni * 8 + cc;
            if (gr0 < nrows) {
                __half2 v = __floats2half2_rn(c[mi][ni][0], c[mi][ni][1]);
                *(__half2*)(out + gr0 * D + col) = v;
            }
            if (gr0 + 8 < nrows) {
                __half2 v = __floats2half2_rn(c[mi][ni][2], c[mi][ni][3]);
                *(__half2*)(out + (gr0 + 8) * D + col) = v;
            }
        }
    }
}

// ---------------- SpMM + bias + relu: one warp/row, fp16 in/out, ILP=4 ------
__global__ void k_spmm(const __half* __restrict__ h, const float* __restrict__ bias,
                       __half* __restrict__ out, int nrows) {
    int w = (blockIdx.x * blockDim.x + threadIdx.x) >> 5;
    int lane = threadIdx.x & 31;
    if (w >= nrows) return;
    int p0 = g_rowptr[w], p1 = g_rowptr[w + 1];
    float4 acc = make_float4(0.f, 0.f, 0.f, 0.f);
    int p = p0;
    for (; p + 4 <= p1; p += 4) {
        int   c0 = g_col[p],     c1 = g_col[p + 1], c2 = g_col[p + 2], c3 = g_col[p + 3];
        float v0 = g_val[p],     v1 = g_val[p + 1], v2 = g_val[p + 2], v3 = g_val[p + 3];
        uint2 r0 = *(const uint2*)(h + c0 * D + lane * 4);
        uint2 r1 = *(const uint2*)(h + c1 * D + lane * 4);
        uint2 r2 = *(const uint2*)(h + c2 * D + lane * 4);
        uint2 r3 = *(const uint2*)(h + c3 * D + lane * 4);
        float2 a0 = __half22float2(*reinterpret_cast<__half2*>(&r0.x));
        float2 b0 = __half22float2(*reinterpret_cast<__half2*>(&r0.y));
        float2 a1 = __half22float2(*reinterpret_cast<__half2*>(&r1.x));
        float2 b1 = __half22float2(*reinterpret_cast<__half2*>(&r1.y));
        float2 a2 = __half22float2(*reinterpret_cast<__half2*>(&r2.x));
        float2 b2 = __half22float2(*reinterpret_cast<__half2*>(&r2.y));
        float2 a3 = __half22float2(*reinterpret_cast<__half2*>(&r3.x));
        float2 b3 = __half22float2(*reinterpret_cast<__half2*>(&r3.y));
        acc.x = fmaf(v0, a0.x, fmaf(v1, a1.x, fmaf(v2, a2.x, fmaf(v3, a3.x, acc.x))));
        acc.y = fmaf(v0, a0.y, fmaf(v1, a1.y, fmaf(v2, a2.y, fmaf(v3, a3.y, acc.y))));
        acc.z = fmaf(v0, b0.x, fmaf(v1, b1.x, fmaf(v2, b2.x, fmaf(v3, b3.x, acc.z))));
        acc.w = fmaf(v0, b0.y, fmaf(v1, b1.y, fmaf(v2, b2.y, fmaf(v3, b3.y, acc.w))));
    }
    for (; p < p1; ++p) {
        int cI = g_col[p]; float vI = g_val[p];
        uint2 rI = *(const uint2*)(h + cI * D + lane * 4);
        float2 fa = __half22float2(*reinterpret_cast<__half2*>(&rI.x));
        float2 fb = __half22float2(*reinterpret_cast<__half2*>(&rI.y));
        acc.x = fmaf(vI, fa.x, acc.x);
        acc.y = fmaf(vI, fa.y, acc.y);
        acc.z = fmaf(vI, fb.x, acc.z);
        acc.w = fmaf(vI, fb.y, acc.w);
    }
    float4 b = *(const float4*)(bias + lane * 4);
    acc.x = fmaxf(acc.x + b.x, 0.f);
    acc.y = fmaxf(acc.y + b.y, 0.f);
    acc.z = fmaxf(acc.z + b.z, 0.f);
    acc.w = fmaxf(acc.w + b.w, 0.f);
    __half2 o0 = __floats2half2_rn(acc.x, acc.y);
    __half2 o1 = __floats2half2_rn(acc.z, acc.w);
    uint2 ov;
    ov.x = *reinterpret_cast<uint32_t*>(&o0);
    ov.y = *reinterpret_cast<uint32_t*>(&o1);
    *(uint2*)(out + w * D + lane * 4) = ov;
}

// ---------------- pool: batch_vec sorted -> contiguous ranges ----------------
__global__ void k_pool(const __half* __restrict__ a, const int* __restrict__ batch,
                       float* __restrict__ out, int n) {
    int g = blockIdx.x, c = threadIdx.x;
    __shared__ int bounds[2];
    if (c < 2) {
        int target = g + c;
        int lo = 0, hi = n;
        while (lo < hi) {
            int mid = (lo + hi) >> 1;
            if (batch[mid] < target) lo = mid + 1; else hi = mid;
        }
        bounds[c] = lo;
    }
    __syncthreads();
    float sum = 0.f;
    for (int r = bounds[0]; r < bounds[1]; ++r) sum += __half2float(a[r * D + c]);
    out[g * D + c] = sum;
}

// ---------------- launch ----------------
extern "C" void kernel_launch(void* const* d_in, const int* in_sizes, int n_in,
                              void* d_out, int out_size) {
    const float* x  = (const float*)d_in[0];
    const float* W1 = (const float*)d_in[1];
    const float* b1 = (const float*)d_in[2];
    const float* W2 = (const float*)d_in[3];
    const float* b2 = (const float*)d_in[4];
    const float* W3 = (const float*)d_in[5];
    const float* b3 = (const float*)d_in[6];
    const int* ei    = (const int*)d_in[7];
    const int* batch = (const int*)d_in[8];
    float* out = (float*)d_out;

    int N = in_sizes[0] / D;
    int E = in_sizes[7] / 2;
    int G = out_size / D;

    __half *xbuf, *hbuf, *abuf;
    cudaGetSymbolAddress((void**)&xbuf, g_x16);
    cudaGetSymbolAddress((void**)&hbuf, g_h16);
    cudaGetSymbolAddress((void**)&abuf, g_a16);

    int smem = 2 * 128 * APITCH * (int)sizeof(__half);  // 69632 B
    cudaFuncSetAttribute(k_gemm_mma, cudaFuncAttributeMaxDynamicSharedMemorySize, smem);

    k_build<<<NB, NT>>>(x, ei, N, E);

    int gb = (N + 127) / 128;
    int sb = (N * 32 + 255) / 256;

    k_gemm_mma<<<gb, 256, smem>>>(xbuf, W1, hbuf, N);
    k_spmm<<<sb, 256>>>(hbuf, b1, abuf, N);
    k_gemm_mma<<<gb, 256, smem>>>(abuf, W2, hbuf, N);
    k_spmm<<<sb, 256>>>(hbuf, b2, abuf, N);
    k_gemm_mma<<<gb, 256, smem>>>(abuf, W3, hbuf, N);
    k_spmm<<<sb, 256>>>(hbuf, b3, abuf, N);

    k_pool<<<G, 128>>>(abuf, batch, out, N);
}

// round 8
// speedup vs baseline: 1.1272x; 1.1272x over previous
#include <cuda_runtime.h>
#include <cuda_fp16.h>
#include <cstdint>

#define NMAX 50000
#define EMAX 800000
#define NNZMAX (EMAX + NMAX)
#define D 128
#define SCAN_B 512
#define APITCH 136   // padded row pitch in halves (272B): conflict-free ldmatrix
#define GB 148       // persistent GEMM blocks (1/SM)

// ---------------- scratch (device globals: allocation-free) ----------------
__device__ __half g_x16[NMAX * D];
__device__ __half g_h16[NMAX * D];
__device__ __half g_a16[NMAX * D];
__device__ __half g_w16[3 * D * D];
__device__ int    g_cnt[NMAX];
__device__ float  g_dis[NMAX];
__device__ int    g_rowptr[NMAX + 1];
__device__ int    g_cursor[NMAX];
__device__ int    g_col[NNZMAX];
__device__ float  g_val[NNZMAX];
__device__ int    g_bsum[128];
__device__ int    g_boff[128];

// ---------------- mma / async helpers ----------------
__device__ __forceinline__ uint32_t smem_u32(const void* p) {
    return (uint32_t)__cvta_generic_to_shared(p);
}
__device__ __forceinline__ void ldmA(uint32_t* r, uint32_t addr) {
    asm volatile("ldmatrix.sync.aligned.m8n8.x4.shared.b16 {%0,%1,%2,%3}, [%4];"
        : "=r"(r[0]), "=r"(r[1]), "=r"(r[2]), "=r"(r[3]) : "r"(addr));
}
__device__ __forceinline__ void ldmB(uint32_t* r, uint32_t addr) {
    asm volatile("ldmatrix.sync.aligned.m8n8.x2.trans.shared.b16 {%0,%1}, [%2];"
        : "=r"(r[0]), "=r"(r[1]) : "r"(addr));
}
__device__ __forceinline__ void mma16816(float* c, const uint32_t* a, const uint32_t* b) {
    asm volatile("mma.sync.aligned.m16n8k16.row.col.f32.f16.f16.f32 "
        "{%0,%1,%2,%3}, {%4,%5,%6,%7}, {%8,%9}, {%0,%1,%2,%3};"
        : "+f"(c[0]), "+f"(c[1]), "+f"(c[2]), "+f"(c[3])
        : "r"(a[0]), "r"(a[1]), "r"(a[2]), "r"(a[3]), "r"(b[0]), "r"(b[1]));
}
__device__ __forceinline__ void cpa16(uint32_t saddr, const void* gaddr, int ssz) {
    asm volatile("cp.async.cg.shared.global [%0], [%1], 16, %2;"
        :: "r"(saddr), "l"(gaddr), "r"(ssz));
}
__device__ __forceinline__ void cpa_commit() {
    asm volatile("cp.async.commit_group;");
}
template <int N>
__device__ __forceinline__ void cpa_wait() {
    asm volatile("cp.async.wait_group %0;" :: "n"(N));
}

// ---------------- CSR build (R6 structure) ----------------
__global__ void k_zero(int n) {
    int i = blockIdx.x * blockDim.x + threadIdx.x;
    if (i < n) g_cnt[i] = 0;
}

__global__ void k_count(const int* __restrict__ dst, int e) {
    int i = blockIdx.x * blockDim.x + threadIdx.x;
    if (i < e) atomicAdd(&g_cnt[dst[i]], 1);
}

__global__ void k_scanA(int n) {
    int t = threadIdx.x;
    int i = blockIdx.x * SCAN_B + t;
    int c = (i < n) ? g_cnt[i] : -1;
    int v = c + 1;
    if (i < n) g_dis[i] = rsqrtf((float)v);
    int s = v;
    #pragma unroll
    for (int o = 16; o; o >>= 1) s += __shfl_down_sync(0xffffffffu, s, o);
    __shared__ int ws[SCAN_B / 32];
    if ((t & 31) == 0) ws[t >> 5] = s;
    __syncthreads();
    if (t < SCAN_B / 32) {
        int x = ws[t];
        #pragma unroll
        for (int o = SCAN_B / 64; o; o >>= 1) x += __shfl_down_sync(0xffffu, x, o);
        if (t == 0) g_bsum[blockIdx.x] = x;
    }
}

__global__ void k_scanB(int nb, int n) {
    __shared__ int s[128];
    int t = threadIdx.x;
    int v = (t < nb) ? g_bsum[t] : 0;
    s[t] = v;
    __syncthreads();
    #pragma unroll
    for (int o = 1; o < 128; o <<= 1) {
        int x = (t >= o) ? s[t - o] : 0;
        __syncthreads();
        s[t] += x;
        __syncthreads();
    }
    g_boff[t] = s[t] - v;
    if (t == 127) g_rowptr[n] = s[127];
}

__global__ void k_scanC(int n) {
    int t = threadIdx.x, b = blockIdx.x;
    int i = b * SCAN_B + t;
    int v = (i < n) ? g_cnt[i] + 1 : 0;
    int lane = t & 31, w = t >> 5;
    int x = v;
    #pragma unroll
    for (int o = 1; o < 32; o <<= 1) {
        int y = __shfl_up_sync(0xffffffffu, x, o);
        if (lane >= o) x += y;
    }
    __shared__ int wsum[SCAN_B / 32];
    if (lane == 31) wsum[w] = x;
    __syncthreads();
    if (t < SCAN_B / 32) {
        int y = wsum[t], z = y;
        #pragma unroll
        for (int o = 1; o < SCAN_B / 32; o <<= 1) {
            int q = __shfl_up_sync(0xffffu, z, o);
            if (t >= o) z += q;
        }
        wsum[t] = z - y;
    }
    __syncthreads();
    int excl = g_boff[b] + wsum[w] + x - v;
    if (i < n) {
        g_rowptr[i] = excl;
        g_col[excl] = i;
        float d_ = g_dis[i];
        g_val[excl] = d_ * d_;
        g_cursor[i] = excl + 1;
    }
}

__global__ void k_fill_edges(const int* __restrict__ src,
                             const int* __restrict__ dst, int e) {
    int i = blockIdx.x * blockDim.x + threadIdx.x;
    if (i < e) {
        int s = src[i];
        int d_ = dst[i];
        int p = atomicAdd(&g_cursor[d_], 1);
        g_col[p] = s;
        g_val[p] = g_dis[s] * g_dis[d_];
    }
}

// ---------------- convert x and W1..W3 to fp16 (one launch) ----------------
__global__ void k_cvt(const float* __restrict__ x,
                      const float* __restrict__ W1,
                      const float* __restrict__ W2,
                      const float* __restrict__ W3, int n4) {
    const int w4 = D * D / 4;  // 4096
    int i = blockIdx.x * blockDim.x + threadIdx.x;
    float4 v;
    uint2* o2;
    int oi;
    if (i < n4) {
        v = ((const float4*)x)[i];
        o2 = (uint2*)g_x16;
        oi = i;
    } else if (i < n4 + 3 * w4) {
        int j = i - n4;
        int w = j / w4, k = j - w * w4;
        const float* W = (w == 0) ? W1 : (w == 1) ? W2 : W3;
        v = ((const float4*)W)[k];
        o2 = (uint2*)(g_w16 + w * D * D);
        oi = k;
    } else return;
    __half2 h0 = __floats2half2_rn(v.x, v.y);
    __half2 h1 = __floats2half2_rn(v.z, v.w);
    uint2 r;
    r.x = *reinterpret_cast<uint32_t*>(&h0);
    r.y = *reinterpret_cast<uint32_t*>(&h1);
    o2[oi] = r;
}

// ---------------- persistent double-buffered HMMA GEMM ----------------------
// grid = GB blocks x 256 thr (8 warps: 4m x 2n). Tile 128x128x128.
// W staged once per block (fp16 copy); A tiles prefetched with cp.async.
__global__ void __launch_bounds__(256, 1)
k_gemm_mma(const __half* __restrict__ in, const __half* __restrict__ W16,
           __half* __restrict__ out, int nrows, int ntiles) {
    extern __shared__ __half sm16[];
    __half* Ws = sm16;                         // 128 x APITCH
    __half* Ab[2] = { sm16 + 128 * APITCH, sm16 + 2 * 128 * APITCH };
    const int t = threadIdx.x;

    // stage W once (raw fp16 copy, padded pitch)
    #pragma unroll
    for (int i = t; i < 128 * 16; i += 256) {
        int r = i >> 4, c8 = i & 15;
        *(uint4*)(Ws + r * APITCH + c8 * 8) = ((const uint4*)W16)[r * 16 + c8];
    }

    const int wid = t >> 5, lane = t & 31;
    const int wm = wid & 3, wn = wid >> 2;
    const int arow = wm * 32 + (lane & 15);
    const int acol_sel = (lane >> 4) * 8;
    const int brow = lane & 15;
    const int bcol0 = wn * 64;
    const int er = lane >> 2, ec = (lane & 3) * 2;

    int tile = blockIdx.x;
    if (tile >= ntiles) return;

    // prefetch first tile into buffer 0
    {
        int row0 = tile * 128;
        #pragma unroll
        for (int j = 0; j < 8; ++j) {
            int i = t + j * 256;
            int r = i >> 4, c8 = i & 15;
            int gr = row0 + r;
            int ok = gr < nrows;
            cpa16(smem_u32(Ab[0] + r * APITCH + c8 * 8),
                  in + (ok ? gr : 0) * D + c8 * 8, ok ? 16 : 0);
        }
        cpa_commit();
    }

    int parity = 0;
    while (tile < ntiles) {
        int next = tile + GB;
        if (next < ntiles) {
            int row0 = next * 128;
            __half* An = Ab[parity ^ 1];
            #pragma unroll
            for (int j = 0; j < 8; ++j) {
                int i = t + j * 256;
                int r = i >> 4, c8 = i & 15;
                int gr = row0 + r;
                int ok = gr < nrows;
                cpa16(smem_u32(An + r * APITCH + c8 * 8),
                      in + (ok ? gr : 0) * D + c8 * 8, ok ? 16 : 0);
            }
            cpa_commit();
            cpa_wait<1>();
        } else {
            cpa_wait<0>();
        }
        __syncthreads();

        const __half* As = Ab[parity];
        float c[2][8][4];
        #pragma unroll
        for (int mi = 0; mi < 2; ++mi)
            #pragma unroll
            for (int ni = 0; ni < 8; ++ni)
                #pragma unroll
                for (int j = 0; j < 4; ++j) c[mi][ni][j] = 0.f;

        #pragma unroll
        for (int k0 = 0; k0 < 128; k0 += 16) {
            uint32_t a[2][4];
            #pragma unroll
            for (int mi = 0; mi < 2; ++mi)
                ldmA(a[mi], smem_u32(As + (arow + mi * 16) * APITCH + k0 + acol_sel));
            uint32_t bf[8][2];
            #pragma unroll
            for (int ni = 0; ni < 8; ++ni)
                ldmB(bf[ni], smem_u32(Ws + (k0 + brow) * APITCH + bcol0 + ni * 8));
            #pragma unroll
            for (int mi = 0; mi < 2; ++mi)
                #pragma unroll
                for (int ni = 0; ni < 8; ++ni)
                    mma16816(c[mi][ni], a[mi], bf[ni]);
        }
        __syncthreads();   // all warps done reading As before it is re-prefetched

        int row0 = tile * 128;
        #pragma unroll
        for (int mi = 0; mi < 2; ++mi) {
            int gr0 = row0 + wm * 32 + mi * 16 + er;
            #pragma unroll
            for (int ni = 0; ni < 8; ++ni) {
                int col = wn * 64 + ni * 8 + ec;
                if (gr0 < nrows) {
                    __half2 v = __floats2half2_rn(c[mi][ni][0], c[mi][ni][1]);
                    *(__half2*)(out + gr0 * D + col) = v;
                }
                if (gr0 + 8 < nrows) {
                    __half2 v = __floats2half2_rn(c[mi][ni][2], c[mi][ni][3]);
                    *(__half2*)(out + (gr0 + 8) * D + col) = v;
                }
            }
        }
        tile = next;
        parity ^= 1;
    }
}

// ---------------- SpMM + bias + relu: one warp/row, fp16 in/out, ILP=4 ------
__global__ void k_spmm(const __half* __restrict__ h, const float* __restrict__ bias,
                       __half* __restrict__ out, int nrows) {
    int w = (blockIdx.x * blockDim.x + threadIdx.x) >> 5;
    int lane = threadIdx.x & 31;
    if (w >= nrows) return;
    int p0 = g_rowptr[w], p1 = g_rowptr[w + 1];
    float4 acc = make_float4(0.f, 0.f, 0.f, 0.f);
    int p = p0;
    for (; p + 4 <= p1; p += 4) {
        int   c0 = g_col[p],     c1 = g_col[p + 1], c2 = g_col[p + 2], c3 = g_col[p + 3];
        float v0 = g_val[p],     v1 = g_val[p + 1], v2 = g_val[p + 2], v3 = g_val[p + 3];
        uint2 r0 = *(const uint2*)(h + c0 * D + lane * 4);
        uint2 r1 = *(const uint2*)(h + c1 * D + lane * 4);
        uint2 r2 = *(const uint2*)(h + c2 * D + lane * 4);
        uint2 r3 = *(const uint2*)(h + c3 * D + lane * 4);
        float2 a0 = __half22float2(*reinterpret_cast<__half2*>(&r0.x));
        float2 b0 = __half22float2(*reinterpret_cast<__half2*>(&r0.y));
        float2 a1 = __half22float2(*reinterpret_cast<__half2*>(&r1.x));
        float2 b1 = __half22float2(*reinterpret_cast<__half2*>(&r1.y));
        float2 a2 = __half22float2(*reinterpret_cast<__half2*>(&r2.x));
        float2 b2 = __half22float2(*reinterpret_cast<__half2*>(&r2.y));
        float2 a3 = __half22float2(*reinterpret_cast<__half2*>(&r3.x));
        float2 b3 = __half22float2(*reinterpret_cast<__half2*>(&r3.y));
        acc.x = fmaf(v0, a0.x, fmaf(v1, a1.x, fmaf(v2, a2.x, fmaf(v3, a3.x, acc.x))));
        acc.y = fmaf(v0, a0.y, fmaf(v1, a1.y, fmaf(v2, a2.y, fmaf(v3, a3.y, acc.y))));
        acc.z = fmaf(v0, b0.x, fmaf(v1, b1.x, fmaf(v2, b2.x, fmaf(v3, b3.x, acc.z))));
        acc.w = fmaf(v0, b0.y, fmaf(v1, b1.y, fmaf(v2, b2.y, fmaf(v3, b3.y, acc.w))));
    }
    for (; p < p1; ++p) {
        int cI = g_col[p]; float vI = g_val[p];
        uint2 rI = *(const uint2*)(h + cI * D + lane * 4);
        float2 fa = __half22float2(*reinterpret_cast<__half2*>(&rI.x));
        float2 fb = __half22float2(*reinterpret_cast<__half2*>(&rI.y));
        acc.x = fmaf(vI, fa.x, acc.x);
        acc.y = fmaf(vI, fa.y, acc.y);
        acc.z = fmaf(vI, fb.x, acc.z);
        acc.w = fmaf(vI, fb.y, acc.w);
    }
    float4 b = *(const float4*)(bias + lane * 4);
    acc.x = fmaxf(acc.x + b.x, 0.f);
    acc.y = fmaxf(acc.y + b.y, 0.f);
    acc.z = fmaxf(acc.z + b.z, 0.f);
    acc.w = fmaxf(acc.w + b.w, 0.f);
    __half2 o0 = __floats2half2_rn(acc.x, acc.y);
    __half2 o1 = __floats2half2_rn(acc.z, acc.w);
    uint2 ov;
    ov.x = *reinterpret_cast<uint32_t*>(&o0);
    ov.y = *reinterpret_cast<uint32_t*>(&o1);
    *(uint2*)(out + w * D + lane * 4) = ov;
}

// ---------------- pool ----------------
__global__ void k_pool(const __half* __restrict__ a, const int* __restrict__ batch,
                       float* __restrict__ out, int n) {
    int g = blockIdx.x, c = threadIdx.x;
    __shared__ int bounds[2];
    if (c < 2) {
        int target = g + c;
        int lo = 0, hi = n;
        while (lo < hi) {
            int mid = (lo + hi) >> 1;
            if (batch[mid] < target) lo = mid + 1; else hi = mid;
        }
        bounds[c] = lo;
    }
    __syncthreads();
    float sum = 0.f;
    for (int r = bounds[0]; r < bounds[1]; ++r) sum += __half2float(a[r * D + c]);
    out[g * D + c] = sum;
}

// ---------------- launch ----------------
extern "C" void kernel_launch(void* const* d_in, const int* in_sizes, int n_in,
                              void* d_out, int out_size) {
    const float* x  = (const float*)d_in[0];
    const float* W1 = (const float*)d_in[1];
    const float* b1 = (const float*)d_in[2];
    const float* W2 = (const float*)d_in[3];
    const float* b2 = (const float*)d_in[4];
    const float* W3 = (const float*)d_in[5];
    const float* b3 = (const float*)d_in[6];
    const int* ei    = (const int*)d_in[7];
    const int* batch = (const int*)d_in[8];
    float* out = (float*)d_out;

    int N = in_sizes[0] / D;
    int E = in_sizes[7] / 2;
    int G = out_size / D;

    __half *xbuf, *hbuf, *abuf, *wbuf;
    cudaGetSymbolAddress((void**)&xbuf, g_x16);
    cudaGetSymbolAddress((void**)&hbuf, g_h16);
    cudaGetSymbolAddress((void**)&abuf, g_a16);
    cudaGetSymbolAddress((void**)&wbuf, g_w16);

    int smem = 3 * 128 * APITCH * (int)sizeof(__half);  // 104448 B
    cudaFuncSetAttribute(k_gemm_mma, cudaFuncAttributeMaxDynamicSharedMemorySize, smem);

    int nb = (N + 255) / 256;
    int eb = (E + 255) / 256;
    int sbk = (N + SCAN_B - 1) / SCAN_B;

    k_zero<<<nb, 256>>>(N);
    k_count<<<eb, 256>>>(ei + E, E);
    k_scanA<<<sbk, SCAN_B>>>(N);
    k_scanB<<<1, 128>>>(sbk, N);
    k_scanC<<<sbk, SCAN_B>>>(N);
    k_fill_edges<<<eb, 256>>>(ei, ei + E, E);

    int n4 = N * D / 4;
    int cvt_total = n4 + 3 * (D * D / 4);
    k_cvt<<<(cvt_total + 255) / 256, 256>>>(x, W1, W2, W3, n4);

    int ntiles = (N + 127) / 128;
    int gb = ntiles < GB ? ntiles : GB;
    int sb = (N * 32 + 255) / 256;

    k_gemm_mma<<<gb, 256, smem>>>(xbuf, wbuf,             hbuf, N, ntiles);
    k_spmm<<<sb, 256>>>(hbuf, b1, abuf, N);
    k_gemm_mma<<<gb, 256, smem>>>(abuf, wbuf + D * D,     hbuf, N, ntiles);
    k_spmm<<<sb, 256>>>(hbuf, b2, abuf, N);
    k_gemm_mma<<<gb, 256, smem>>>(abuf, wbuf + 2 * D * D, hbuf, N, ntiles);
    k_spmm<<<sb, 256>>>(hbuf, b3, abuf, N);

    k_pool<<<G, 128>>>(abuf, batch, out, N);
}

// round 9
// speedup vs baseline: 1.1380x; 1.0095x over previous
#include <cuda_runtime.h>
#include <cuda_fp16.h>
#include <cstdint>

#define NMAX 50000
#define EMAX 800000
#define NNZMAX (EMAX + NMAX)
#define D 128
#define SCAN_B 512
#define APITCH 136   // padded row pitch in halves (272B): conflict-free ldmatrix
#define GB 148       // persistent GEMM blocks (1/SM)

// ---------------- scratch (device globals: allocation-free) ----------------
__device__ __half g_x16[NMAX * D];
__device__ __half g_h16[NMAX * D];
__device__ __half g_a16[NMAX * D];
__device__ __half g_w16[3 * D * D];
__device__ int    g_cnt[NMAX];
__device__ float  g_dis[NMAX];
__device__ int    g_rowptr[NMAX + 1];
__device__ int    g_cursor[NMAX];
__device__ int    g_col[NNZMAX];
__device__ float  g_val[NNZMAX];
__device__ int    g_bsum[128];

// ---------------- mma / async helpers ----------------
__device__ __forceinline__ uint32_t smem_u32(const void* p) {
    return (uint32_t)__cvta_generic_to_shared(p);
}
__device__ __forceinline__ void ldmA(uint32_t* r, uint32_t addr) {
    asm volatile("ldmatrix.sync.aligned.m8n8.x4.shared.b16 {%0,%1,%2,%3}, [%4];"
        : "=r"(r[0]), "=r"(r[1]), "=r"(r[2]), "=r"(r[3]) : "r"(addr));
}
__device__ __forceinline__ void ldmB(uint32_t* r, uint32_t addr) {
    asm volatile("ldmatrix.sync.aligned.m8n8.x2.trans.shared.b16 {%0,%1}, [%2];"
        : "=r"(r[0]), "=r"(r[1]) : "r"(addr));
}
__device__ __forceinline__ void mma16816(float* c, const uint32_t* a, const uint32_t* b) {
    asm volatile("mma.sync.aligned.m16n8k16.row.col.f32.f16.f16.f32 "
        "{%0,%1,%2,%3}, {%4,%5,%6,%7}, {%8,%9}, {%0,%1,%2,%3};"
        : "+f"(c[0]), "+f"(c[1]), "+f"(c[2]), "+f"(c[3])
        : "r"(a[0]), "r"(a[1]), "r"(a[2]), "r"(a[3]), "r"(b[0]), "r"(b[1]));
}
__device__ __forceinline__ void cpa16(uint32_t saddr, const void* gaddr, int ssz) {
    asm volatile("cp.async.cg.shared.global [%0], [%1], 16, %2;"
        :: "r"(saddr), "l"(gaddr), "r"(ssz));
}
__device__ __forceinline__ void cpa_commit() {
    asm volatile("cp.async.commit_group;");
}
template <int N>
__device__ __forceinline__ void cpa_wait() {
    asm volatile("cp.async.wait_group %0;" :: "n"(N));
}

// ---------------- fused convert (x, W1..3) + zero counts --------------------
__global__ void k_cvtzero(const float* __restrict__ x,
                          const float* __restrict__ W1,
                          const float* __restrict__ W2,
                          const float* __restrict__ W3, int n4, int n) {
    const int w4 = D * D / 4;  // 4096
    int i = blockIdx.x * blockDim.x + threadIdx.x;
    if (i < n) g_cnt[i] = 0;
    float4 v;
    uint2* o2;
    int oi;
    if (i < n4) {
        v = ((const float4*)x)[i];
        o2 = (uint2*)g_x16;
        oi = i;
    } else if (i < n4 + 3 * w4) {
        int j = i - n4;
        int w = j / w4, k = j - w * w4;
        const float* W = (w == 0) ? W1 : (w == 1) ? W2 : W3;
        v = ((const float4*)W)[k];
        o2 = (uint2*)(g_w16 + w * D * D);
        oi = k;
    } else return;
    __half2 h0 = __floats2half2_rn(v.x, v.y);
    __half2 h1 = __floats2half2_rn(v.z, v.w);
    uint2 r;
    r.x = *reinterpret_cast<uint32_t*>(&h0);
    r.y = *reinterpret_cast<uint32_t*>(&h1);
    o2[oi] = r;
}

__global__ void k_count(const int* __restrict__ dst, int e) {
    int i = blockIdx.x * blockDim.x + threadIdx.x;
    if (i < e) atomicAdd(&g_cnt[dst[i]], 1);
}

// Pass A: per-block sums of (cnt+1); also dis = rsqrt(deg)
__global__ void k_scanA(int n) {
    int t = threadIdx.x;
    int i = blockIdx.x * SCAN_B + t;
    int c = (i < n) ? g_cnt[i] : -1;
    int v = c + 1;
    if (i < n) g_dis[i] = rsqrtf((float)v);
    int s = v;
    #pragma unroll
    for (int o = 16; o; o >>= 1) s += __shfl_down_sync(0xffffffffu, s, o);
    __shared__ int ws[SCAN_B / 32];
    if ((t & 31) == 0) ws[t >> 5] = s;
    __syncthreads();
    if (t < SCAN_B / 32) {
        int x = ws[t];
        #pragma unroll
        for (int o = SCAN_B / 64; o; o >>= 1) x += __shfl_down_sync(0xffffu, x, o);
        if (t == 0) g_bsum[blockIdx.x] = x;
    }
}

// Pass C: block offset computed inline (reduce bsum[0..b-1]); local scan;
// writes rowptr, self-loop entry, cursor. Last block writes rowptr[n].
__global__ void k_scanC(int n) {
    int t = threadIdx.x, b = blockIdx.x;
    int i = b * SCAN_B + t;
    int v = (i < n) ? g_cnt[i] + 1 : 0;
    int lane = t & 31, w = t >> 5;

    // inline block offset: sum of bsum[0..b-1] (and full sum for last block)
    __shared__ int s_boff, s_total;
    {
        int nb = gridDim.x;
        int part = 0, full = 0;
        for (int j = t; j < nb; j += SCAN_B) {
            int bs = g_bsum[j];
            full += bs;
            if (j < b) part += bs;
        }
        #pragma unroll
        for (int o = 16; o; o >>= 1) {
            part += __shfl_down_sync(0xffffffffu, part, o);
            full += __shfl_down_sync(0xffffffffu, full, o);
        }
        __shared__ int wp[SCAN_B / 32], wf[SCAN_B / 32];
        if (lane == 0) { wp[w] = part; wf[w] = full; }
        __syncthreads();
        if (t == 0) {
            int sp = 0, sf = 0;
            #pragma unroll
            for (int j = 0; j < SCAN_B / 32; ++j) { sp += wp[j]; sf += wf[j]; }
            s_boff = sp;
            s_total = sf;
        }
    }

    int x = v;
    #pragma unroll
    for (int o = 1; o < 32; o <<= 1) {
        int y = __shfl_up_sync(0xffffffffu, x, o);
        if (lane >= o) x += y;
    }
    __shared__ int wsum[SCAN_B / 32];
    if (lane == 31) wsum[w] = x;
    __syncthreads();
    if (t < SCAN_B / 32) {
        int y = wsum[t], z = y;
        #pragma unroll
        for (int o = 1; o < SCAN_B / 32; o <<= 1) {
            int q = __shfl_up_sync(0xffffu, z, o);
            if (t >= o) z += q;
        }
        wsum[t] = z - y;
    }
    __syncthreads();
    int excl = s_boff + wsum[w] + x - v;
    if (i < n) {
        g_rowptr[i] = excl;
        g_col[excl] = i;
        float d_ = g_dis[i];
        g_val[excl] = d_ * d_;
        g_cursor[i] = excl + 1;
    }
    if (b == gridDim.x - 1 && t == 0) g_rowptr[n] = s_total;
}

__global__ void k_fill_edges(const int* __restrict__ src,
                             const int* __restrict__ dst, int e) {
    int i = blockIdx.x * blockDim.x + threadIdx.x;
    if (i < e) {
        int s = src[i];
        int d_ = dst[i];
        int p = atomicAdd(&g_cursor[d_], 1);
        g_col[p] = s;
        g_val[p] = g_dis[s] * g_dis[d_];
    }
}

// ---------------- persistent double-buffered HMMA GEMM (512 thr, 16 warps) --
// warps: 4m x 4n; per warp 32(m) x 32(n); tile 128x128x128
__global__ void __launch_bounds__(512, 1)
k_gemm_mma(const __half* __restrict__ in, const __half* __restrict__ W16,
           __half* __restrict__ out, int nrows, int ntiles) {
    extern __shared__ __half sm16[];
    __half* Ws = sm16;                         // 128 x APITCH
    __half* Ab[2] = { sm16 + 128 * APITCH, sm16 + 2 * 128 * APITCH };
    const int t = threadIdx.x;

    // stage W once (raw fp16 copy, padded pitch): 2048 uint4, 4/thread
    #pragma unroll
    for (int i = t; i < 128 * 16; i += 512) {
        int r = i >> 4, c8 = i & 15;
        *(uint4*)(Ws + r * APITCH + c8 * 8) = ((const uint4*)W16)[r * 16 + c8];
    }

    const int wid = t >> 5, lane = t & 31;
    const int wm = wid & 3, wn = wid >> 2;      // 4 x 4
    const int arow = wm * 32 + (lane & 15);
    const int acol_sel = (lane >> 4) * 8;
    const int brow = lane & 15;
    const int bcol0 = wn * 32;
    const int er = lane >> 2, ec = (lane & 3) * 2;

    int tile = blockIdx.x;
    if (tile >= ntiles) return;

    {
        int row0 = tile * 128;
        #pragma unroll
        for (int j = 0; j < 4; ++j) {
            int i = t + j * 512;
            int r = i >> 4, c8 = i & 15;
            int gr = row0 + r;
            int ok = gr < nrows;
            cpa16(smem_u32(Ab[0] + r * APITCH + c8 * 8),
                  in + (ok ? gr : 0) * D + c8 * 8, ok ? 16 : 0);
        }
        cpa_commit();
    }

    int parity = 0;
    while (tile < ntiles) {
        int next = tile + GB;
        if (next < ntiles) {
            int row0 = next * 128;
            __half* An = Ab[parity ^ 1];
            #pragma unroll
            for (int j = 0; j < 4; ++j) {
                int i = t + j * 512;
                int r = i >> 4, c8 = i & 15;
                int gr = row0 + r;
                int ok = gr < nrows;
                cpa16(smem_u32(An + r * APITCH + c8 * 8),
                      in + (ok ? gr : 0) * D + c8 * 8, ok ? 16 : 0);
            }
            cpa_commit();
            cpa_wait<1>();
        } else {
            cpa_wait<0>();
        }
        __syncthreads();

        const __half* As = Ab[parity];
        float c[2][4][4];
        #pragma unroll
        for (int mi = 0; mi < 2; ++mi)
            #pragma unroll
            for (int ni = 0; ni < 4; ++ni)
                #pragma unroll
                for (int j = 0; j < 4; ++j) c[mi][ni][j] = 0.f;

        #pragma unroll
        for (int k0 = 0; k0 < 128; k0 += 16) {
            uint32_t a[2][4];
            #pragma unroll
            for (int mi = 0; mi < 2; ++mi)
                ldmA(a[mi], smem_u32(As + (arow + mi * 16) * APITCH + k0 + acol_sel));
            uint32_t bf[4][2];
            #pragma unroll
            for (int ni = 0; ni < 4; ++ni)
                ldmB(bf[ni], smem_u32(Ws + (k0 + brow) * APITCH + bcol0 + ni * 8));
            #pragma unroll
            for (int mi = 0; mi < 2; ++mi)
                #pragma unroll
                for (int ni = 0; ni < 4; ++ni)
                    mma16816(c[mi][ni], a[mi], bf[ni]);
        }
        __syncthreads();   // all warps done reading As before re-prefetch

        int row0 = tile * 128;
        #pragma unroll
        for (int mi = 0; mi < 2; ++mi) {
            int gr0 = row0 + wm * 32 + mi * 16 + er;
            #pragma unroll
            for (int ni = 0; ni < 4; ++ni) {
                int col = wn * 32 + ni * 8 + ec;
                if (gr0 < nrows) {
                    __half2 v = __floats2half2_rn(c[mi][ni][0], c[mi][ni][1]);
                    *(__half2*)(out + gr0 * D + col) = v;
                }
                if (gr0 + 8 < nrows) {
                    __half2 v = __floats2half2_rn(c[mi][ni][2], c[mi][ni][3]);
                    *(__half2*)(out + (gr0 + 8) * D + col) = v;
                }
            }
        }
        tile = next;
        parity ^= 1;
    }
}

// ---------------- SpMM + bias + relu: one warp/row, fp16 in/out, ILP=4 ------
__global__ void k_spmm(const __half* __restrict__ h, const float* __restrict__ bias,
                       __half* __restrict__ out, int nrows) {
    int w = (blockIdx.x * blockDim.x + threadIdx.x) >> 5;
    int lane = threadIdx.x & 31;
    if (w >= nrows) return;
    int p0 = g_rowptr[w], p1 = g_rowptr[w + 1];
    float4 acc = make_float4(0.f, 0.f, 0.f, 0.f);
    int p = p0;
    for (; p + 4 <= p1; p += 4) {
        int   c0 = g_col[p],     c1 = g_col[p + 1], c2 = g_col[p + 2], c3 = g_col[p + 3];
        float v0 = g_val[p],     v1 = g_val[p + 1], v2 = g_val[p + 2], v3 = g_val[p + 3];
        uint2 r0 = *(const uint2*)(h + c0 * D + lane * 4);
        uint2 r1 = *(const uint2*)(h + c1 * D + lane * 4);
        uint2 r2 = *(const uint2*)(h + c2 * D + lane * 4);
        uint2 r3 = *(const uint2*)(h + c3 * D + lane * 4);
        float2 a0 = __half22float2(*reinterpret_cast<__half2*>(&r0.x));
        float2 b0 = __half22float2(*reinterpret_cast<__half2*>(&r0.y));
        float2 a1 = __half22float2(*reinterpret_cast<__half2*>(&r1.x));
        float2 b1 = __half22float2(*reinterpret_cast<__half2*>(&r1.y));
        float2 a2 = __half22float2(*reinterpret_cast<__half2*>(&r2.x));
        float2 b2 = __half22float2(*reinterpret_cast<__half2*>(&r2.y));
        float2 a3 = __half22float2(*reinterpret_cast<__half2*>(&r3.x));
        float2 b3 = __half22float2(*reinterpret_cast<__half2*>(&r3.y));
        acc.x = fmaf(v0, a0.x, fmaf(v1, a1.x, fmaf(v2, a2.x, fmaf(v3, a3.x, acc.x))));
        acc.y = fmaf(v0, a0.y, fmaf(v1, a1.y, fmaf(v2, a2.y, fmaf(v3, a3.y, acc.y))));
        acc.z = fmaf(v0, b0.x, fmaf(v1, b1.x, fmaf(v2, b2.x, fmaf(v3, b3.x, acc.z))));
        acc.w = fmaf(v0, b0.y, fmaf(v1, b1.y, fmaf(v2, b2.y, fmaf(v3, b3.y, acc.w))));
    }
    for (; p < p1; ++p) {
        int cI = g_col[p]; float vI = g_val[p];
        uint2 rI = *(const uint2*)(h + cI * D + lane * 4);
        float2 fa = __half22float2(*reinterpret_cast<__half2*>(&rI.x));
        float2 fb = __half22float2(*reinterpret_cast<__half2*>(&rI.y));
        acc.x = fmaf(vI, fa.x, acc.x);
        acc.y = fmaf(vI, fa.y, acc.y);
        acc.z = fmaf(vI, fb.x, acc.z);
        acc.w = fmaf(vI, fb.y, acc.w);
    }
    float4 b = *(const float4*)(bias + lane * 4);
    acc.x = fmaxf(acc.x + b.x, 0.f);
    acc.y = fmaxf(acc.y + b.y, 0.f);
    acc.z = fmaxf(acc.z + b.z, 0.f);
    acc.w = fmaxf(acc.w + b.w, 0.f);
    __half2 o0 = __floats2half2_rn(acc.x, acc.y);
    __half2 o1 = __floats2half2_rn(acc.z, acc.w);
    uint2 ov;
    ov.x = *reinterpret_cast<uint32_t*>(&o0);
    ov.y = *reinterpret_cast<uint32_t*>(&o1);
    *(uint2*)(out + w * D + lane * 4) = ov;
}

// ---------------- pool ----------------
__global__ void k_pool(const __half* __restrict__ a, const int* __restrict__ batch,
                       float* __restrict__ out, int n) {
    int g = blockIdx.x, c = threadIdx.x;
    __shared__ int bounds[2];
    if (c < 2) {
        int target = g + c;
        int lo = 0, hi = n;
        while (lo < hi) {
            int mid = (lo + hi) >> 1;
            if (batch[mid] < target) lo = mid + 1; else hi = mid;
        }
        bounds[c] = lo;
    }
    __syncthreads();
    float sum = 0.f;
    for (int r = bounds[0]; r < bounds[1]; ++r) sum += __half2float(a[r * D + c]);
    out[g * D + c] = sum;
}

// ---------------- launch ----------------
extern "C" void kernel_launch(void* const* d_in, const int* in_sizes, int n_in,
                              void* d_out, int out_size) {
    const float* x  = (const float*)d_in[0];
    const float* W1 = (const float*)d_in[1];
    const float* b1 = (const float*)d_in[2];
    const float* W2 = (const float*)d_in[3];
    const float* b2 = (const float*)d_in[4];
    const float* W3 = (const float*)d_in[5];
    const float* b3 = (const float*)d_in[6];
    const int* ei    = (const int*)d_in[7];
    const int* batch = (const int*)d_in[8];
    float* out = (float*)d_out;

    int N = in_sizes[0] / D;
    int E = in_sizes[7] / 2;
    int G = out_size / D;

    __half *xbuf, *hbuf, *abuf, *wbuf;
    cudaGetSymbolAddress((void**)&xbuf, g_x16);
    cudaGetSymbolAddress((void**)&hbuf, g_h16);
    cudaGetSymbolAddress((void**)&abuf, g_a16);
    cudaGetSymbolAddress((void**)&wbuf, g_w16);

    int smem = 3 * 128 * APITCH * (int)sizeof(__half);  // 104448 B
    cudaFuncSetAttribute(k_gemm_mma, cudaFuncAttributeMaxDynamicSharedMemorySize, smem);

    int eb = (E + 255) / 256;
    int sbk = (N + SCAN_B - 1) / SCAN_B;

    int n4 = N * D / 4;
    int cvt_total = n4 + 3 * (D * D / 4);
    k_cvtzero<<<(cvt_total + 255) / 256, 256>>>(x, W1, W2, W3, n4, N);
    k_count<<<eb, 256>>>(ei + E, E);
    k_scanA<<<sbk, SCAN_B>>>(N);
    k_scanC<<<sbk, SCAN_B>>>(N);
    k_fill_edges<<<eb, 256>>>(ei, ei + E, E);

    int ntiles = (N + 127) / 128;
    int gb = ntiles < GB ? ntiles : GB;
    int sb = (N * 32 + 255) / 256;

    k_gemm_mma<<<gb, 512, smem>>>(xbuf, wbuf,             hbuf, N, ntiles);
    k_spmm<<<sb, 256>>>(hbuf, b1, abuf, N);
    k_gemm_mma<<<gb, 512, smem>>>(abuf, wbuf + D * D,     hbuf, N, ntiles);
    k_spmm<<<sb, 256>>>(hbuf, b2, abuf, N);
    k_gemm_mma<<<gb, 512, smem>>>(abuf, wbuf + 2 * D * D, hbuf, N, ntiles);
    k_spmm<<<sb, 256>>>(hbuf, b3, abuf, N);

    k_pool<<<G, 128>>>(abuf, batch, out, N);
}

// round 10
// speedup vs baseline: 1.1580x; 1.0176x over previous
#include <cuda_runtime.h>
#include <cuda_fp16.h>
#include <cstdint>

#define NMAX 50000
#define EMAX 800000
#define NNZMAX (EMAX + NMAX)
#define D 128
#define SCAN_B 512
#define APITCH 136   // padded row pitch in halves (272B): conflict-free ldmatrix
#define GB 148       // persistent GEMM blocks (1/SM)

// ---------------- scratch (device globals: allocation-free) ----------------
__device__ __half g_x16[NMAX * D];
__device__ __half g_h16[NMAX * D];
__device__ __half g_a16[NMAX * D];
__device__ __half g_w16[3 * D * D];
__device__ int    g_cnt[NMAX];
__device__ float  g_dis[NMAX];
__device__ int    g_rowptr[NMAX + 1];
__device__ int    g_cursor[NMAX];
__device__ int    g_col[NNZMAX];
__device__ float  g_val[NNZMAX];
__device__ int    g_bsum[128];

// ---------------- mma / async helpers ----------------
__device__ __forceinline__ uint32_t smem_u32(const void* p) {
    return (uint32_t)__cvta_generic_to_shared(p);
}
__device__ __forceinline__ void ldmA(uint32_t* r, uint32_t addr) {
    asm volatile("ldmatrix.sync.aligned.m8n8.x4.shared.b16 {%0,%1,%2,%3}, [%4];"
        : "=r"(r[0]), "=r"(r[1]), "=r"(r[2]), "=r"(r[3]) : "r"(addr));
}
__device__ __forceinline__ void ldmB(uint32_t* r, uint32_t addr) {
    asm volatile("ldmatrix.sync.aligned.m8n8.x2.trans.shared.b16 {%0,%1}, [%2];"
        : "=r"(r[0]), "=r"(r[1]) : "r"(addr));
}
__device__ __forceinline__ void mma16816(float* c, const uint32_t* a, const uint32_t* b) {
    asm volatile("mma.sync.aligned.m16n8k16.row.col.f32.f16.f16.f32 "
        "{%0,%1,%2,%3}, {%4,%5,%6,%7}, {%8,%9}, {%0,%1,%2,%3};"
        : "+f"(c[0]), "+f"(c[1]), "+f"(c[2]), "+f"(c[3])
        : "r"(a[0]), "r"(a[1]), "r"(a[2]), "r"(a[3]), "r"(b[0]), "r"(b[1]));
}
__device__ __forceinline__ void cpa16(uint32_t saddr, const void* gaddr, int ssz) {
    asm volatile("cp.async.cg.shared.global [%0], [%1], 16, %2;"
        :: "r"(saddr), "l"(gaddr), "r"(ssz));
}
__device__ __forceinline__ void cpa_commit() {
    asm volatile("cp.async.commit_group;");
}
template <int N>
__device__ __forceinline__ void cpa_wait() {
    asm volatile("cp.async.wait_group %0;" :: "n"(N));
}

// ---------------- CSR build chain (stream B) ----------------
__global__ void k_zero(int n) {
    int i = blockIdx.x * blockDim.x + threadIdx.x;
    if (i < n) g_cnt[i] = 0;
}

__global__ void k_count(const int* __restrict__ dst, int e) {
    int i = blockIdx.x * blockDim.x + threadIdx.x;
    if (i < e) atomicAdd(&g_cnt[dst[i]], 1);
}

__global__ void k_scanA(int n) {
    int t = threadIdx.x;
    int i = blockIdx.x * SCAN_B + t;
    int c = (i < n) ? g_cnt[i] : -1;
    int v = c + 1;
    if (i < n) g_dis[i] = rsqrtf((float)v);
    int s = v;
    #pragma unroll
    for (int o = 16; o; o >>= 1) s += __shfl_down_sync(0xffffffffu, s, o);
    __shared__ int ws[SCAN_B / 32];
    if ((t & 31) == 0) ws[t >> 5] = s;
    __syncthreads();
    if (t < SCAN_B / 32) {
        int x = ws[t];
        #pragma unroll
        for (int o = SCAN_B / 64; o; o >>= 1) x += __shfl_down_sync(0xffffu, x, o);
        if (t == 0) g_bsum[blockIdx.x] = x;
    }
}

__global__ void k_scanC(int n) {
    int t = threadIdx.x, b = blockIdx.x;
    int i = b * SCAN_B + t;
    int v = (i < n) ? g_cnt[i] + 1 : 0;
    int lane = t & 31, w = t >> 5;

    __shared__ int s_boff, s_total;
    {
        int nb = gridDim.x;
        int part = 0, full = 0;
        for (int j = t; j < nb; j += SCAN_B) {
            int bs = g_bsum[j];
            full += bs;
            if (j < b) part += bs;
        }
        #pragma unroll
        for (int o = 16; o; o >>= 1) {
            part += __shfl_down_sync(0xffffffffu, part, o);
            full += __shfl_down_sync(0xffffffffu, full, o);
        }
        __shared__ int wp[SCAN_B / 32], wf[SCAN_B / 32];
        if (lane == 0) { wp[w] = part; wf[w] = full; }
        __syncthreads();
        if (t == 0) {
            int sp = 0, sf = 0;
            #pragma unroll
            for (int j = 0; j < SCAN_B / 32; ++j) { sp += wp[j]; sf += wf[j]; }
            s_boff = sp;
            s_total = sf;
        }
    }

    int x = v;
    #pragma unroll
    for (int o = 1; o < 32; o <<= 1) {
        int y = __shfl_up_sync(0xffffffffu, x, o);
        if (lane >= o) x += y;
    }
    __shared__ int wsum[SCAN_B / 32];
    if (lane == 31) wsum[w] = x;
    __syncthreads();
    if (t < SCAN_B / 32) {
        int y = wsum[t], z = y;
        #pragma unroll
        for (int o = 1; o < SCAN_B / 32; o <<= 1) {
            int q = __shfl_up_sync(0xffffu, z, o);
            if (t >= o) z += q;
        }
        wsum[t] = z - y;
    }
    __syncthreads();
    int excl = s_boff + wsum[w] + x - v;
    if (i < n) {
        g_rowptr[i] = excl;
        g_col[excl] = i;
        float d_ = g_dis[i];
        g_val[excl] = d_ * d_;
        g_cursor[i] = excl + 1;
    }
    if (b == gridDim.x - 1 && t == 0) g_rowptr[n] = s_total;
}

__global__ void k_fill_edges(const int* __restrict__ src,
                             const int* __restrict__ dst, int e) {
    int i = blockIdx.x * blockDim.x + threadIdx.x;
    if (i < e) {
        int s = src[i];
        int d_ = dst[i];
        int p = atomicAdd(&g_cursor[d_], 1);
        g_col[p] = s;
        g_val[p] = g_dis[s] * g_dis[d_];
    }
}

// ---------------- convert x, W1..3 to fp16 (main stream) --------------------
__global__ void k_cvt(const float* __restrict__ x,
                      const float* __restrict__ W1,
                      const float* __restrict__ W2,
                      const float* __restrict__ W3, int n4) {
    const int w4 = D * D / 4;  // 4096
    int i = blockIdx.x * blockDim.x + threadIdx.x;
    float4 v;
    uint2* o2;
    int oi;
    if (i < n4) {
        v = ((const float4*)x)[i];
        o2 = (uint2*)g_x16;
        oi = i;
    } else if (i < n4 + 3 * w4) {
        int j = i - n4;
        int w = j / w4, k = j - w * w4;
        const float* W = (w == 0) ? W1 : (w == 1) ? W2 : W3;
        v = ((const float4*)W)[k];
        o2 = (uint2*)(g_w16 + w * D * D);
        oi = k;
    } else return;
    __half2 h0 = __floats2half2_rn(v.x, v.y);
    __half2 h1 = __floats2half2_rn(v.z, v.w);
    uint2 r;
    r.x = *reinterpret_cast<uint32_t*>(&h0);
    r.y = *reinterpret_cast<uint32_t*>(&h1);
    o2[oi] = r;
}

// ---------------- persistent double-buffered HMMA GEMM (512 thr, 16 warps) --
__global__ void __launch_bounds__(512, 1)
k_gemm_mma(const __half* __restrict__ in, const __half* __restrict__ W16,
           __half* __restrict__ out, int nrows, int ntiles) {
    extern __shared__ __half sm16[];
    __half* Ws = sm16;                         // 128 x APITCH
    __half* Ab[2] = { sm16 + 128 * APITCH, sm16 + 2 * 128 * APITCH };
    const int t = threadIdx.x;

    #pragma unroll
    for (int i = t; i < 128 * 16; i += 512) {
        int r = i >> 4, c8 = i & 15;
        *(uint4*)(Ws + r * APITCH + c8 * 8) = ((const uint4*)W16)[r * 16 + c8];
    }

    const int wid = t >> 5, lane = t & 31;
    const int wm = wid & 3, wn = wid >> 2;      // 4 x 4
    const int arow = wm * 32 + (lane & 15);
    const int acol_sel = (lane >> 4) * 8;
    const int brow = lane & 15;
    const int bcol0 = wn * 32;
    const int er = lane >> 2, ec = (lane & 3) * 2;

    int tile = blockIdx.x;
    if (tile >= ntiles) return;

    {
        int row0 = tile * 128;
        #pragma unroll
        for (int j = 0; j < 4; ++j) {
            int i = t + j * 512;
            int r = i >> 4, c8 = i & 15;
            int gr = row0 + r;
            int ok = gr < nrows;
            cpa16(smem_u32(Ab[0] + r * APITCH + c8 * 8),
                  in + (ok ? gr : 0) * D + c8 * 8, ok ? 16 : 0);
        }
        cpa_commit();
    }

    int parity = 0;
    while (tile < ntiles) {
        int next = tile + GB;
        if (next < ntiles) {
            int row0 = next * 128;
            __half* An = Ab[parity ^ 1];
            #pragma unroll
            for (int j = 0; j < 4; ++j) {
                int i = t + j * 512;
                int r = i >> 4, c8 = i & 15;
                int gr = row0 + r;
                int ok = gr < nrows;
                cpa16(smem_u32(An + r * APITCH + c8 * 8),
                      in + (ok ? gr : 0) * D + c8 * 8, ok ? 16 : 0);
            }
            cpa_commit();
            cpa_wait<1>();
        } else {
            cpa_wait<0>();
        }
        __syncthreads();

        const __half* As = Ab[parity];
        float c[2][4][4];
        #pragma unroll
        for (int mi = 0; mi < 2; ++mi)
            #pragma unroll
            for (int ni = 0; ni < 4; ++ni)
                #pragma unroll
                for (int j = 0; j < 4; ++j) c[mi][ni][j] = 0.f;

        #pragma unroll
        for (int k0 = 0; k0 < 128; k0 += 16) {
            uint32_t a[2][4];
            #pragma unroll
            for (int mi = 0; mi < 2; ++mi)
                ldmA(a[mi], smem_u32(As + (arow + mi * 16) * APITCH + k0 + acol_sel));
            uint32_t bf[4][2];
            #pragma unroll
            for (int ni = 0; ni < 4; ++ni)
                ldmB(bf[ni], smem_u32(Ws + (k0 + brow) * APITCH + bcol0 + ni * 8));
            #pragma unroll
            for (int mi = 0; mi < 2; ++mi)
                #pragma unroll
                for (int ni = 0; ni < 4; ++ni)
                    mma16816(c[mi][ni], a[mi], bf[ni]);
        }
        __syncthreads();

        int row0 = tile * 128;
        #pragma unroll
        for (int mi = 0; mi < 2; ++mi) {
            int gr0 = row0 + wm * 32 + mi * 16 + er;
            #pragma unroll
            for (int ni = 0; ni < 4; ++ni) {
                int col = wn * 32 + ni * 8 + ec;
                if (gr0 < nrows) {
                    __half2 v = __floats2half2_rn(c[mi][ni][0], c[mi][ni][1]);
                    *(__half2*)(out + gr0 * D + col) = v;
                }
                if (gr0 + 8 < nrows) {
                    __half2 v = __floats2half2_rn(c[mi][ni][2], c[mi][ni][3]);
                    *(__half2*)(out + (gr0 + 8) * D + col) = v;
                }
            }
        }
        tile = next;
        parity ^= 1;
    }
}

// ---------------- SpMM + bias + relu: one warp/row, fp16 in/out, ILP=4 ------
__global__ void k_spmm(const __half* __restrict__ h, const float* __restrict__ bias,
                       __half* __restrict__ out, int nrows) {
    int w = (blockIdx.x * blockDim.x + threadIdx.x) >> 5;
    int lane = threadIdx.x & 31;
    if (w >= nrows) return;
    int p0 = g_rowptr[w], p1 = g_rowptr[w + 1];
    float4 acc = make_float4(0.f, 0.f, 0.f, 0.f);
    int p = p0;
    for (; p + 4 <= p1; p += 4) {
        int   c0 = g_col[p],     c1 = g_col[p + 1], c2 = g_col[p + 2], c3 = g_col[p + 3];
        float v0 = g_val[p],     v1 = g_val[p + 1], v2 = g_val[p + 2], v3 = g_val[p + 3];
        uint2 r0 = *(const uint2*)(h + c0 * D + lane * 4);
        uint2 r1 = *(const uint2*)(h + c1 * D + lane * 4);
        uint2 r2 = *(const uint2*)(h + c2 * D + lane * 4);
        uint2 r3 = *(const uint2*)(h + c3 * D + lane * 4);
        float2 a0 = __half22float2(*reinterpret_cast<__half2*>(&r0.x));
        float2 b0 = __half22float2(*reinterpret_cast<__half2*>(&r0.y));
        float2 a1 = __half22float2(*reinterpret_cast<__half2*>(&r1.x));
        float2 b1 = __half22float2(*reinterpret_cast<__half2*>(&r1.y));
        float2 a2 = __half22float2(*reinterpret_cast<__half2*>(&r2.x));
        float2 b2 = __half22float2(*reinterpret_cast<__half2*>(&r2.y));
        float2 a3 = __half22float2(*reinterpret_cast<__half2*>(&r3.x));
        float2 b3 = __half22float2(*reinterpret_cast<__half2*>(&r3.y));
        acc.x = fmaf(v0, a0.x, fmaf(v1, a1.x, fmaf(v2, a2.x, fmaf(v3, a3.x, acc.x))));
        acc.y = fmaf(v0, a0.y, fmaf(v1, a1.y, fmaf(v2, a2.y, fmaf(v3, a3.y, acc.y))));
        acc.z = fmaf(v0, b0.x, fmaf(v1, b1.x, fmaf(v2, b2.x, fmaf(v3, b3.x, acc.z))));
        acc.w = fmaf(v0, b0.y, fmaf(v1, b1.y, fmaf(v2, b2.y, fmaf(v3, b3.y, acc.w))));
    }
    for (; p < p1; ++p) {
        int cI = g_col[p]; float vI = g_val[p];
        uint2 rI = *(const uint2*)(h + cI * D + lane * 4);
        float2 fa = __half22float2(*reinterpret_cast<__half2*>(&rI.x));
        float2 fb = __half22float2(*reinterpret_cast<__half2*>(&rI.y));
        acc.x = fmaf(vI, fa.x, acc.x);
        acc.y = fmaf(vI, fa.y, acc.y);
        acc.z = fmaf(vI, fb.x, acc.z);
        acc.w = fmaf(vI, fb.y, acc.w);
    }
    float4 b = *(const float4*)(bias + lane * 4);
    acc.x = fmaxf(acc.x + b.x, 0.f);
    acc.y = fmaxf(acc.y + b.y, 0.f);
    acc.z = fmaxf(acc.z + b.z, 0.f);
    acc.w = fmaxf(acc.w + b.w, 0.f);
    __half2 o0 = __floats2half2_rn(acc.x, acc.y);
    __half2 o1 = __floats2half2_rn(acc.z, acc.w);
    uint2 ov;
    ov.x = *reinterpret_cast<uint32_t*>(&o0);
    ov.y = *reinterpret_cast<uint32_t*>(&o1);
    *(uint2*)(out + w * D + lane * 4) = ov;
}

// ---------------- pool ----------------
__global__ void k_pool(const __half* __restrict__ a, const int* __restrict__ batch,
                       float* __restrict__ out, int n) {
    int g = blockIdx.x, c = threadIdx.x;
    __shared__ int bounds[2];
    if (c < 2) {
        int target = g + c;
        int lo = 0, hi = n;
        while (lo < hi) {
            int mid = (lo + hi) >> 1;
            if (batch[mid] < target) lo = mid + 1; else hi = mid;
        }
        bounds[c] = lo;
    }
    __syncthreads();
    float sum = 0.f;
    for (int r = bounds[0]; r < bounds[1]; ++r) sum += __half2float(a[r * D + c]);
    out[g * D + c] = sum;
}

// ---------------- launch ----------------
extern "C" void kernel_launch(void* const* d_in, const int* in_sizes, int n_in,
                              void* d_out, int out_size) {
    const float* x  = (const float*)d_in[0];
    const float* W1 = (const float*)d_in[1];
    const float* b1 = (const float*)d_in[2];
    const float* W2 = (const float*)d_in[3];
    const float* b2 = (const float*)d_in[4];
    const float* W3 = (const float*)d_in[5];
    const float* b3 = (const float*)d_in[6];
    const int* ei    = (const int*)d_in[7];
    const int* batch = (const int*)d_in[8];
    float* out = (float*)d_out;

    int N = in_sizes[0] / D;
    int E = in_sizes[7] / 2;
    int G = out_size / D;

    __half *xbuf, *hbuf, *abuf, *wbuf;
    cudaGetSymbolAddress((void**)&xbuf, g_x16);
    cudaGetSymbolAddress((void**)&hbuf, g_h16);
    cudaGetSymbolAddress((void**)&abuf, g_a16);
    cudaGetSymbolAddress((void**)&wbuf, g_w16);

    int smem = 3 * 128 * APITCH * (int)sizeof(__half);  // 104448 B
    cudaFuncSetAttribute(k_gemm_mma, cudaFuncAttributeMaxDynamicSharedMemorySize, smem);

    // one-time host objects (host-side only; no device memory involved)
    static cudaStream_t s2 = nullptr;
    static cudaEvent_t evFork = nullptr, evJoin = nullptr;
    if (s2 == nullptr) {
        cudaStreamCreateWithFlags(&s2, cudaStreamNonBlocking);
        cudaEventCreateWithFlags(&evFork, cudaEventDisableTiming);
        cudaEventCreateWithFlags(&evJoin, cudaEventDisableTiming);
    }

    int nb = (N + 255) / 256;
    int eb = (E + 255) / 256;
    int sbk = (N + SCAN_B - 1) / SCAN_B;
    int n4 = N * D / 4;
    int cvt_total = n4 + 3 * (D * D / 4);
    int ntiles = (N + 127) / 128;
    int gb = ntiles < GB ? ntiles : GB;
    int sb = (N * 32 + 511) / 512;

    // fork: CSR chain on s2, concurrent with cvt+gemm1 on main stream
    cudaEventRecord(evFork, 0);
    cudaStreamWaitEvent(s2, evFork, 0);
    k_zero<<<nb, 256, 0, s2>>>(N);
    k_count<<<eb, 256, 0, s2>>>(ei + E, E);
    k_scanA<<<sbk, SCAN_B, 0, s2>>>(N);
    k_scanC<<<sbk, SCAN_B, 0, s2>>>(N);
    k_fill_edges<<<eb, 256, 0, s2>>>(ei, ei + E, E);
    cudaEventRecord(evJoin, s2);

    k_cvt<<<(cvt_total + 255) / 256, 256>>>(x, W1, W2, W3, n4);
    k_gemm_mma<<<gb, 512, smem>>>(xbuf, wbuf, hbuf, N, ntiles);

    // join: spmm needs both gemm1 (main) and CSR (s2)
    cudaStreamWaitEvent(0, evJoin, 0);

    k_spmm<<<sb, 512>>>(hbuf, b1, abuf, N);
    k_gemm_mma<<<gb, 512, smem>>>(abuf, wbuf + D * D,     hbuf, N, ntiles);
    k_spmm<<<sb, 512>>>(hbuf, b2, abuf, N);
    k_gemm_mma<<<gb, 512, smem>>>(abuf, wbuf + 2 * D * D, hbuf, N, ntiles);
    k_spmm<<<sb, 512>>>(hbuf, b3, abuf, N);

    k_pool<<<G, 128>>>(abuf, batch, out, N);
}